// round 2
// baseline (speedup 1.0000x reference)
#include <cuda_runtime.h>

#define B_ 2
#define M_ 2048
#define D_ 256
#define H_ 8
#define DK_ 32
#define L_ 4
#define FF_ 512
#define R_ (B_*M_)
#define LN_EPS 1e-5f

// ---------------- scratch (static device globals; no allocation) ----------------
__device__ float g_x  [R_*D_];
__device__ float g_q  [R_*D_];
__device__ float g_k  [R_*D_];
__device__ float g_v  [R_*D_];
__device__ float g_att[R_*D_];
__device__ float g_ff1[R_*FF_];
__device__ float g_ff2[R_*D_];

// ---------------- simple copy ----------------
__global__ void copy_kernel(const float* __restrict__ src, float* __restrict__ dst, int n)
{
    int i = blockIdx.x * blockDim.x + threadIdx.x;
    if (i < n) dst[i] = src[i];
}

// ---------------- tiled GEMM: C[RxN] = A[RxK] @ W[KxN] + bias (opt ReLU) ----------------
// grid: (R/64, N/64), 256 threads, BK=16, 4x4 micro-tile per thread
__global__ __launch_bounds__(256) void gemm_kernel(
    const float* __restrict__ A, const float* __restrict__ W,
    const float* __restrict__ bias, float* __restrict__ C,
    int K, int N, int relu)
{
    __shared__ float As[16][64];   // As[k][row]
    __shared__ float Bs[16][64];   // Bs[k][col]

    int tid  = threadIdx.x;
    int row0 = blockIdx.x * 64, col0 = blockIdx.y * 64;
    int tx = tid & 15, ty = tid >> 4;
    int ar = tid >> 2, ac = (tid & 3) * 4;   // A tile: 64x16, one float4/thread
    int br = tid >> 4, bc = (tid & 15) * 4;  // B tile: 16x64, one float4/thread

    float acc[4][4] = {};

    for (int k0 = 0; k0 < K; k0 += 16) {
        float4 av = *(const float4*)&A[(size_t)(row0 + ar) * K + k0 + ac];
        float4 bv = *(const float4*)&W[(size_t)(k0 + br) * N + col0 + bc];
        __syncthreads();
        As[ac + 0][ar] = av.x; As[ac + 1][ar] = av.y;
        As[ac + 2][ar] = av.z; As[ac + 3][ar] = av.w;
        *(float4*)&Bs[br][bc] = bv;
        __syncthreads();
#pragma unroll
        for (int kk = 0; kk < 16; kk++) {
            float4 a = *(const float4*)&As[kk][ty * 4];
            float4 b = *(const float4*)&Bs[kk][tx * 4];
            acc[0][0] += a.x * b.x; acc[0][1] += a.x * b.y; acc[0][2] += a.x * b.z; acc[0][3] += a.x * b.w;
            acc[1][0] += a.y * b.x; acc[1][1] += a.y * b.y; acc[1][2] += a.y * b.z; acc[1][3] += a.y * b.w;
            acc[2][0] += a.z * b.x; acc[2][1] += a.z * b.y; acc[2][2] += a.z * b.z; acc[2][3] += a.z * b.w;
            acc[3][0] += a.w * b.x; acc[3][1] += a.w * b.y; acc[3][2] += a.w * b.z; acc[3][3] += a.w * b.w;
        }
    }

    float4 bb = *(const float4*)&bias[col0 + tx * 4];
#pragma unroll
    for (int i = 0; i < 4; i++) {
        float4 r;
        r.x = acc[i][0] + bb.x;
        r.y = acc[i][1] + bb.y;
        r.z = acc[i][2] + bb.z;
        r.w = acc[i][3] + bb.w;
        if (relu) {
            r.x = fmaxf(r.x, 0.f); r.y = fmaxf(r.y, 0.f);
            r.z = fmaxf(r.z, 0.f); r.w = fmaxf(r.w, 0.f);
        }
        *(float4*)&C[(size_t)(row0 + ty * 4 + i) * N + col0 + tx * 4] = r;
    }
}

// ---------------- flash attention with fused geometric bias ----------------
// scores[m,n] = (q.k)/sqrt(dk) + alpha * (coords_m . coords_n)
// Fold: Q pre-scaled by 1/sqrt(dk); rows 32..34 of the transposed tiles hold
// alpha*coords (Q side) and coords (K side); row 35 is zero padding.
// grid: (M/64, B*H), 256 threads. Each block: 64 queries x one head.
__global__ __launch_bounds__(256) void attn_kernel(
    const float* __restrict__ Q, const float* __restrict__ Kg,
    const float* __restrict__ V, const float* __restrict__ coords,
    const float* __restrict__ alpha_arr, int layer, float* __restrict__ O)
{
    __shared__ float Qst[36][64];   // [k][qrow]
    __shared__ float Kst[36][64];   // [k][krow]
    __shared__ float Vs[64][36];    // [krow][d]  (stride 36 to reduce store conflicts)
    __shared__ float Ps[64][64];    // exp(scores)
    __shared__ float row_m[64], row_l[64], row_c[64];

    int tid = threadIdx.x;
    int bh  = blockIdx.y;
    int b   = bh >> 3, h = bh & 7;
    int q0  = blockIdx.x * 64;
    const float scale = 0.17677669529663687f;  // 1/sqrt(32)

    int lr = tid >> 2;          // load row 0..63
    int lc = (tid & 3) * 8;     // load col base 0,8,16,24

    // --- Q tile (pre-scaled), transposed into smem ---
    {
        const float* qp = &Q[(size_t)(b * M_ + q0 + lr) * D_ + h * DK_ + lc];
        float4 a = *(const float4*)&qp[0];
        float4 c = *(const float4*)&qp[4];
        Qst[lc + 0][lr] = a.x * scale; Qst[lc + 1][lr] = a.y * scale;
        Qst[lc + 2][lr] = a.z * scale; Qst[lc + 3][lr] = a.w * scale;
        Qst[lc + 4][lr] = c.x * scale; Qst[lc + 5][lr] = c.y * scale;
        Qst[lc + 6][lr] = c.z * scale; Qst[lc + 7][lr] = c.w * scale;
    }
    if (tid < 64) {
        float al = alpha_arr[layer];
        const float* cp = &coords[(size_t)(b * M_ + q0 + tid) * 3];
        Qst[32][tid] = al * cp[0];
        Qst[33][tid] = al * cp[1];
        Qst[34][tid] = al * cp[2];
        Qst[35][tid] = 0.f;
        row_m[tid] = -3.0e38f;
        row_l[tid] = 0.f;
    }

    int ty = tid >> 4, tx = tid & 15;       // S-phase layout: 16x16, 4x4 micro
    int orow = tid >> 2, oc = (tid & 3) * 8; // O-phase layout: 64x4, 8 cols each
    float o[8] = {};

    for (int kt = 0; kt < M_ / 64; kt++) {
        int k0 = kt * 64;
        __syncthreads();   // previous O-phase done before overwriting K/V tiles

        // --- load K (transposed), V, coords(K side) ---
        {
            const float* kp = &Kg[(size_t)(b * M_ + k0 + lr) * D_ + h * DK_ + lc];
            float4 a = *(const float4*)&kp[0];
            float4 c = *(const float4*)&kp[4];
            Kst[lc + 0][lr] = a.x; Kst[lc + 1][lr] = a.y;
            Kst[lc + 2][lr] = a.z; Kst[lc + 3][lr] = a.w;
            Kst[lc + 4][lr] = c.x; Kst[lc + 5][lr] = c.y;
            Kst[lc + 6][lr] = c.z; Kst[lc + 7][lr] = c.w;
            const float* vp = &V[(size_t)(b * M_ + k0 + lr) * D_ + h * DK_ + lc];
            float4 va = *(const float4*)&vp[0];
            float4 vb = *(const float4*)&vp[4];
            *(float4*)&Vs[lr][lc]     = va;
            *(float4*)&Vs[lr][lc + 4] = vb;
        }
        if (tid < 64) {
            const float* cp = &coords[(size_t)(b * M_ + k0 + tid) * 3];
            Kst[32][tid] = cp[0];
            Kst[33][tid] = cp[1];
            Kst[34][tid] = cp[2];
            Kst[35][tid] = 0.f;
        }
        __syncthreads();

        // --- S = Q K^T + bias (unified 36-deep dot) ---
        float s[4][4] = {};
#pragma unroll
        for (int kk = 0; kk < 36; kk++) {
            float4 a  = *(const float4*)&Qst[kk][ty * 4];
            float4 bk = *(const float4*)&Kst[kk][tx * 4];
            s[0][0] += a.x * bk.x; s[0][1] += a.x * bk.y; s[0][2] += a.x * bk.z; s[0][3] += a.x * bk.w;
            s[1][0] += a.y * bk.x; s[1][1] += a.y * bk.y; s[1][2] += a.y * bk.z; s[1][3] += a.y * bk.w;
            s[2][0] += a.z * bk.x; s[2][1] += a.z * bk.y; s[2][2] += a.z * bk.z; s[2][3] += a.z * bk.w;
            s[3][0] += a.w * bk.x; s[3][1] += a.w * bk.y; s[3][2] += a.w * bk.z; s[3][3] += a.w * bk.w;
        }

        // --- online softmax (row reductions across the 16 tx lanes) ---
#pragma unroll
        for (int i = 0; i < 4; i++) {
            int r = ty * 4 + i;
            float mx = fmaxf(fmaxf(s[i][0], s[i][1]), fmaxf(s[i][2], s[i][3]));
            mx = fmaxf(mx, __shfl_xor_sync(0xffffffffu, mx, 1));
            mx = fmaxf(mx, __shfl_xor_sync(0xffffffffu, mx, 2));
            mx = fmaxf(mx, __shfl_xor_sync(0xffffffffu, mx, 4));
            mx = fmaxf(mx, __shfl_xor_sync(0xffffffffu, mx, 8));
            float mo = row_m[r];
            float mn = fmaxf(mo, mx);
            float sum = 0.f;
#pragma unroll
            for (int j = 0; j < 4; j++) {
                s[i][j] = __expf(s[i][j] - mn);
                sum += s[i][j];
            }
            sum += __shfl_xor_sync(0xffffffffu, sum, 1);
            sum += __shfl_xor_sync(0xffffffffu, sum, 2);
            sum += __shfl_xor_sync(0xffffffffu, sum, 4);
            sum += __shfl_xor_sync(0xffffffffu, sum, 8);
            if (tx == 0) {
                float corr = __expf(mo - mn);
                row_c[r] = corr;
                row_l[r] = row_l[r] * corr + sum;
                row_m[r] = mn;
            }
            *(float4*)&Ps[r][tx * 4] = make_float4(s[i][0], s[i][1], s[i][2], s[i][3]);
        }
        __syncthreads();

        // --- O = corr*O + P @ V ---
        float corr = row_c[orow];
#pragma unroll
        for (int c = 0; c < 8; c++) o[c] *= corr;
#pragma unroll
        for (int n4 = 0; n4 < 16; n4++) {
            float4 p = *(const float4*)&Ps[orow][n4 * 4];
#pragma unroll
            for (int t = 0; t < 4; t++) {
                float pt = (t == 0) ? p.x : (t == 1) ? p.y : (t == 2) ? p.z : p.w;
                float4 va = *(const float4*)&Vs[n4 * 4 + t][oc];
                float4 vb = *(const float4*)&Vs[n4 * 4 + t][oc + 4];
                o[0] += pt * va.x; o[1] += pt * va.y; o[2] += pt * va.z; o[3] += pt * va.w;
                o[4] += pt * vb.x; o[5] += pt * vb.y; o[6] += pt * vb.z; o[7] += pt * vb.w;
            }
        }
    }

    // --- normalize and store ---
    float linv = 1.f / row_l[orow];
    float* op = &O[(size_t)(b * M_ + q0 + orow) * D_ + h * DK_ + oc];
    float4 r0 = make_float4(o[0] * linv, o[1] * linv, o[2] * linv, o[3] * linv);
    float4 r1 = make_float4(o[4] * linv, o[5] * linv, o[6] * linv, o[7] * linv);
    *(float4*)&op[0] = r0;
    *(float4*)&op[4] = r1;
}

// ---------------- fused residual + LayerNorm (warp per row) ----------------
__global__ __launch_bounds__(256) void add_ln_kernel(
    const float* __restrict__ xin, const float* __restrict__ res,
    const float* __restrict__ gamma, const float* __restrict__ beta,
    float* __restrict__ xout)
{
    int warp = threadIdx.x >> 5, lane = threadIdx.x & 31;
    int row = blockIdx.x * 8 + warp;

    const float4* px = (const float4*)(xin + (size_t)row * D_) + lane * 2;
    const float4* pr = (const float4*)(res + (size_t)row * D_) + lane * 2;
    float4 x0 = px[0], x1 = px[1], r0 = pr[0], r1 = pr[1];
    float v[8] = { x0.x + r0.x, x0.y + r0.y, x0.z + r0.z, x0.w + r0.w,
                   x1.x + r1.x, x1.y + r1.y, x1.z + r1.z, x1.w + r1.w };

    float s = 0.f, q = 0.f;
#pragma unroll
    for (int c = 0; c < 8; c++) { s += v[c]; q += v[c] * v[c]; }
#pragma unroll
    for (int off = 16; off > 0; off >>= 1) {
        s += __shfl_xor_sync(0xffffffffu, s, off);
        q += __shfl_xor_sync(0xffffffffu, q, off);
    }
    float mu  = s * (1.f / D_);
    float var = q * (1.f / D_) - mu * mu;
    float rs  = rsqrtf(var + LN_EPS);

    const float4* pg = (const float4*)gamma + lane * 2;
    const float4* pb = (const float4*)beta  + lane * 2;
    float4 g0 = pg[0], g1 = pg[1], b0 = pb[0], b1 = pb[1];

    float4 o0, o1;
    o0.x = (v[0] - mu) * rs * g0.x + b0.x;
    o0.y = (v[1] - mu) * rs * g0.y + b0.y;
    o0.z = (v[2] - mu) * rs * g0.z + b0.z;
    o0.w = (v[3] - mu) * rs * g0.w + b0.w;
    o1.x = (v[4] - mu) * rs * g1.x + b1.x;
    o1.y = (v[5] - mu) * rs * g1.y + b1.y;
    o1.z = (v[6] - mu) * rs * g1.z + b1.z;
    o1.w = (v[7] - mu) * rs * g1.w + b1.w;

    float4* po = (float4*)(xout + (size_t)row * D_) + lane * 2;
    po[0] = o0;
    po[1] = o1;
}

// ---------------- host launcher ----------------
extern "C" void kernel_launch(void* const* d_in, const int* in_sizes, int n_in,
                              void* d_out, int out_size)
{
    const float* x      = (const float*)d_in[0];
    const float* coords = (const float*)d_in[1];
    const float* wq     = (const float*)d_in[2];
    const float* bq     = (const float*)d_in[3];
    const float* wk     = (const float*)d_in[4];
    const float* bk     = (const float*)d_in[5];
    const float* wv     = (const float*)d_in[6];
    const float* bv     = (const float*)d_in[7];
    const float* alpha  = (const float*)d_in[8];
    const float* w1     = (const float*)d_in[9];
    const float* b1     = (const float*)d_in[10];
    const float* w2     = (const float*)d_in[11];
    const float* b2     = (const float*)d_in[12];
    const float* ln1g   = (const float*)d_in[13];
    const float* ln1b   = (const float*)d_in[14];
    const float* ln2g   = (const float*)d_in[15];
    const float* ln2b   = (const float*)d_in[16];
    float* out = (float*)d_out;

    float *gx, *gq, *gk, *gv, *gatt, *gff1, *gff2;
    cudaGetSymbolAddress((void**)&gx,   g_x);
    cudaGetSymbolAddress((void**)&gq,   g_q);
    cudaGetSymbolAddress((void**)&gk,   g_k);
    cudaGetSymbolAddress((void**)&gv,   g_v);
    cudaGetSymbolAddress((void**)&gatt, g_att);
    cudaGetSymbolAddress((void**)&gff1, g_ff1);
    cudaGetSymbolAddress((void**)&gff2, g_ff2);

    copy_kernel<<<(R_ * D_ + 255) / 256, 256>>>(x, gx, R_ * D_);

    for (int i = 0; i < L_; i++) {
        dim3 g_qkv(R_ / 64, D_ / 64);
        gemm_kernel<<<g_qkv, 256>>>(gx, wq + (size_t)i * D_ * D_, bq + i * D_, gq, D_, D_, 0);
        gemm_kernel<<<g_qkv, 256>>>(gx, wk + (size_t)i * D_ * D_, bk + i * D_, gk, D_, D_, 0);
        gemm_kernel<<<g_qkv, 256>>>(gx, wv + (size_t)i * D_ * D_, bv + i * D_, gv, D_, D_, 0);

        attn_kernel<<<dim3(M_ / 64, B_ * H_), 256>>>(gq, gk, gv, coords, alpha, i, gatt);

        add_ln_kernel<<<R_ / 8, 256>>>(gx, gatt, ln1g + i * D_, ln1b + i * D_, gx);

        gemm_kernel<<<dim3(R_ / 64, FF_ / 64), 256>>>(gx, w1 + (size_t)i * D_ * FF_, b1 + i * FF_, gff1, D_, FF_, 1);
        gemm_kernel<<<dim3(R_ / 64, D_ / 64), 256>>>(gff1, w2 + (size_t)i * FF_ * D_, b2 + i * D_, gff2, FF_, D_, 0);

        float* xout = (i == L_ - 1) ? out : gx;
        add_ln_kernel<<<R_ / 8, 256>>>(gx, gff2, ln2g + i * D_, ln2b + i * D_, xout);
    }
}

// round 3
// speedup vs baseline: 2.5733x; 2.5733x over previous
#include <cuda_runtime.h>

#define B_ 2
#define M_ 2048
#define D_ 256
#define H_ 8
#define DK_ 32
#define L_ 4
#define FF_ 512
#define R_ (B_*M_)
#define LN_EPS 1e-5f

// ---------------- scratch (static device globals; no allocation) ----------------
__device__ float g_x  [R_*D_];
__device__ float g_q  [R_*D_];
__device__ float g_k  [R_*D_];
__device__ float g_v  [R_*D_];
__device__ float g_att[R_*D_];
__device__ float g_ff1[R_*FF_];
__device__ float g_ff2[R_*D_];

// ---------------- tf32 helpers ----------------
__device__ __forceinline__ unsigned f2tf(float x) {
    unsigned u;
    asm("cvt.rna.tf32.f32 %0, %1;" : "=r"(u) : "f"(x));
    return u;
}

__device__ __forceinline__ void mma_tf32(float d[4], const unsigned a[4], const unsigned b[2]) {
    asm volatile(
        "mma.sync.aligned.m16n8k8.row.col.f32.tf32.tf32.f32 "
        "{%0,%1,%2,%3}, {%4,%5,%6,%7}, {%8,%9}, {%0,%1,%2,%3};"
        : "+f"(d[0]), "+f"(d[1]), "+f"(d[2]), "+f"(d[3])
        : "r"(a[0]), "r"(a[1]), "r"(a[2]), "r"(a[3]), "r"(b[0]), "r"(b[1]));
}

// ---------------- simple copy ----------------
__global__ void copy_kernel(const float* __restrict__ src, float* __restrict__ dst, int n)
{
    int i = blockIdx.x * blockDim.x + threadIdx.x;
    if (i < n) dst[i] = src[i];
}

// ---------------- TF32 tensor-core GEMM: C[RxN] = A[RxK] @ W[KxN] + bias (opt ReLU) ----------------
// grid: (R/128, N/64), 256 threads (8 warps in 4x2), BK=32
__global__ __launch_bounds__(256) void gemm_tc(
    const float* __restrict__ A, const float* __restrict__ W,
    const float* __restrict__ bias, float* __restrict__ C,
    int K, int N, int relu)
{
    __shared__ unsigned As[128][36];   // stride 36 = 4 mod 32 -> conflict-free A-frag loads
    __shared__ unsigned Ws[32][72];    // stride 72 = 8 mod 32 -> conflict-free B-frag loads

    int tid  = threadIdx.x;
    int warp = tid >> 5, lane = tid & 31;
    int g = lane >> 2, tig = lane & 3;
    int wm = warp >> 1, wn = warp & 1;
    int row0 = blockIdx.x * 128, col0 = blockIdx.y * 64;

    int arow = tid >> 1, acol = (tid & 1) * 16;     // A tile loader: 128x32
    int wrow = tid >> 3, wcol = (tid & 7) * 8;      // W tile loader: 32x64

    float acc[2][4][4] = {};

    for (int kb = 0; kb < K; kb += 32) {
        const float* ap = &A[(size_t)(row0 + arow) * K + kb + acol];
        float4 a0 = *(const float4*)&ap[0];
        float4 a1 = *(const float4*)&ap[4];
        float4 a2 = *(const float4*)&ap[8];
        float4 a3 = *(const float4*)&ap[12];
        const float* wp = &W[(size_t)(kb + wrow) * N + col0 + wcol];
        float4 w0 = *(const float4*)&wp[0];
        float4 w1 = *(const float4*)&wp[4];
        __syncthreads();   // prior compute done before overwrite
        {
            uint4 u;
            u.x = f2tf(a0.x); u.y = f2tf(a0.y); u.z = f2tf(a0.z); u.w = f2tf(a0.w);
            *(uint4*)&As[arow][acol + 0] = u;
            u.x = f2tf(a1.x); u.y = f2tf(a1.y); u.z = f2tf(a1.z); u.w = f2tf(a1.w);
            *(uint4*)&As[arow][acol + 4] = u;
            u.x = f2tf(a2.x); u.y = f2tf(a2.y); u.z = f2tf(a2.z); u.w = f2tf(a2.w);
            *(uint4*)&As[arow][acol + 8] = u;
            u.x = f2tf(a3.x); u.y = f2tf(a3.y); u.z = f2tf(a3.z); u.w = f2tf(a3.w);
            *(uint4*)&As[arow][acol + 12] = u;
            u.x = f2tf(w0.x); u.y = f2tf(w0.y); u.z = f2tf(w0.z); u.w = f2tf(w0.w);
            *(uint4*)&Ws[wrow][wcol + 0] = u;
            u.x = f2tf(w1.x); u.y = f2tf(w1.y); u.z = f2tf(w1.z); u.w = f2tf(w1.w);
            *(uint4*)&Ws[wrow][wcol + 4] = u;
        }
        __syncthreads();

#pragma unroll
        for (int ks = 0; ks < 4; ks++) {
            unsigned af[2][4];
#pragma unroll
            for (int mt = 0; mt < 2; mt++) {
                int r = wm * 32 + mt * 16;
                af[mt][0] = As[r + g][ks * 8 + tig];
                af[mt][1] = As[r + g + 8][ks * 8 + tig];
                af[mt][2] = As[r + g][ks * 8 + tig + 4];
                af[mt][3] = As[r + g + 8][ks * 8 + tig + 4];
            }
            unsigned bf[4][2];
#pragma unroll
            for (int nt = 0; nt < 4; nt++) {
                int c = wn * 32 + nt * 8;
                bf[nt][0] = Ws[ks * 8 + tig][c + g];
                bf[nt][1] = Ws[ks * 8 + tig + 4][c + g];
            }
#pragma unroll
            for (int mt = 0; mt < 2; mt++)
#pragma unroll
                for (int nt = 0; nt < 4; nt++)
                    mma_tf32(acc[mt][nt], af[mt], bf[nt]);
        }
    }

    // epilogue: bias (+ReLU), STG.64
#pragma unroll
    for (int nt = 0; nt < 4; nt++) {
        int c = col0 + wn * 32 + nt * 8 + 2 * tig;
        float b0 = bias[c], b1 = bias[c + 1];
#pragma unroll
        for (int mt = 0; mt < 2; mt++) {
            int r = row0 + wm * 32 + mt * 16 + g;
            float v0 = acc[mt][nt][0] + b0;
            float v1 = acc[mt][nt][1] + b1;
            float v2 = acc[mt][nt][2] + b0;
            float v3 = acc[mt][nt][3] + b1;
            if (relu) {
                v0 = fmaxf(v0, 0.f); v1 = fmaxf(v1, 0.f);
                v2 = fmaxf(v2, 0.f); v3 = fmaxf(v3, 0.f);
            }
            *(float2*)&C[(size_t)r * N + c]       = make_float2(v0, v1);
            *(float2*)&C[(size_t)(r + 8) * N + c] = make_float2(v2, v3);
        }
    }
}

// ---------------- TF32 flash attention with fused geometric bias ----------------
// scores = (q.k)/sqrt(dk) + alpha*(cq.ck). Q pre-scaled; k-dims 32..34 carry
// alpha*coords (Q side) / coords (K side); dims 35..39 zero pad (K=40, 5 k8-steps).
// grid: (M/64, B*H), 128 threads (4 warps x 16 query rows).
__global__ __launch_bounds__(128) void attn_tc(
    const float* __restrict__ Q, const float* __restrict__ Kg,
    const float* __restrict__ V, const float* __restrict__ coords,
    const float* __restrict__ alpha_arr, int layer, float* __restrict__ O)
{
    __shared__ unsigned Kt[40][72];   // K^T (+bias rows), stride 72 = 8 mod 32
    __shared__ unsigned Vs[64][40];   // V, stride 40 = 8 mod 32
    __shared__ unsigned Ps[64][68];   // P (tf32 bits), stride 68 = 4 mod 32

    int tid  = threadIdx.x;
    int warp = tid >> 5, lane = tid & 31;
    int g = lane >> 2, tig = lane & 3;
    int bh = blockIdx.y, b = bh >> 3, h = bh & 7;
    int q0 = blockIdx.x * 64;
    const float scale = 0.17677669529663687f;  // 1/sqrt(32)
    float alpha = __ldg(alpha_arr + layer);

    int rg  = q0 + warp * 16 + g;       // this thread's two query rows: rg, rg+8
    size_t qbase = (size_t)(b * M_ + rg) * D_ + h * DK_;

    // --- Q fragments in registers (constant across K loop) ---
    unsigned qa[5][4];
#pragma unroll
    for (int ks = 0; ks < 4; ks++) {
        int c0 = ks * 8 + tig;
        qa[ks][0] = f2tf(Q[qbase + c0] * scale);
        qa[ks][1] = f2tf(Q[qbase + 8 * (size_t)D_ + c0] * scale);
        qa[ks][2] = f2tf(Q[qbase + c0 + 4] * scale);
        qa[ks][3] = f2tf(Q[qbase + 8 * (size_t)D_ + c0 + 4] * scale);
    }
    {   // ks=4: k-dims 32..34 = alpha*coords, 35..39 = 0
        float v0 = (tig < 3) ? alpha * coords[(size_t)(b * M_ + rg) * 3 + tig] : 0.f;
        float v1 = (tig < 3) ? alpha * coords[(size_t)(b * M_ + rg + 8) * 3 + tig] : 0.f;
        qa[4][0] = f2tf(v0);
        qa[4][1] = f2tf(v1);
        qa[4][2] = 0u;
        qa[4][3] = 0u;
    }

    float m0 = -1e30f, m1 = -1e30f, l0 = 0.f, l1 = 0.f;
    float oacc[4][4] = {};

    int lr = tid >> 1, half = tid & 1;   // K/V tile loaders

    for (int kt = 0; kt < M_ / 64; kt++) {
        int k0 = kt * 64;
        __syncthreads();   // prev iter's MMA reads of Kt/Vs/Ps done

        // --- load K (transposed, cvt) and V (cvt) ---
        {
            const float* kp = &Kg[(size_t)(b * M_ + k0 + lr) * D_ + h * DK_ + half * 16];
#pragma unroll
            for (int j = 0; j < 16; j++) Kt[half * 16 + j][lr] = f2tf(kp[j]);
            const float* vp = &V[(size_t)(b * M_ + k0 + lr) * D_ + h * DK_ + half * 16];
#pragma unroll
            for (int j = 0; j < 4; j++) {
                float4 v4 = *(const float4*)&vp[j * 4];
                uint4 u;
                u.x = f2tf(v4.x); u.y = f2tf(v4.y); u.z = f2tf(v4.z); u.w = f2tf(v4.w);
                *(uint4*)&Vs[lr][half * 16 + j * 4] = u;
            }
        }
        if (tid < 64) {
            const float* cp = &coords[(size_t)(b * M_ + k0 + tid) * 3];
            Kt[32][tid] = f2tf(cp[0]);
            Kt[33][tid] = f2tf(cp[1]);
            Kt[34][tid] = f2tf(cp[2]);
            Kt[35][tid] = 0u; Kt[36][tid] = 0u; Kt[37][tid] = 0u;
            Kt[38][tid] = 0u; Kt[39][tid] = 0u;
        }
        __syncthreads();

        // --- S = Q K^T + bias ---
        float s[8][4] = {};
#pragma unroll
        for (int nt = 0; nt < 8; nt++) {
#pragma unroll
            for (int ks = 0; ks < 5; ks++) {
                unsigned bf[2];
                bf[0] = Kt[ks * 8 + tig][nt * 8 + g];
                bf[1] = Kt[ks * 8 + tig + 4][nt * 8 + g];
                mma_tf32(s[nt], qa[ks], bf);
            }
        }

        // --- online softmax (rows rg and rg+8; 4 tig lanes share each row) ---
        float mx0 = -1e30f, mx1 = -1e30f;
#pragma unroll
        for (int nt = 0; nt < 8; nt++) {
            mx0 = fmaxf(mx0, fmaxf(s[nt][0], s[nt][1]));
            mx1 = fmaxf(mx1, fmaxf(s[nt][2], s[nt][3]));
        }
        mx0 = fmaxf(mx0, __shfl_xor_sync(0xffffffffu, mx0, 1));
        mx0 = fmaxf(mx0, __shfl_xor_sync(0xffffffffu, mx0, 2));
        mx1 = fmaxf(mx1, __shfl_xor_sync(0xffffffffu, mx1, 1));
        mx1 = fmaxf(mx1, __shfl_xor_sync(0xffffffffu, mx1, 2));

        float mn0 = fmaxf(m0, mx0), mn1 = fmaxf(m1, mx1);
        float corr0 = __expf(m0 - mn0), corr1 = __expf(m1 - mn1);
        m0 = mn0; m1 = mn1;

        float sum0 = 0.f, sum1 = 0.f;
        int pr0 = warp * 16 + g, pr1 = pr0 + 8;
#pragma unroll
        for (int nt = 0; nt < 8; nt++) {
            float p0 = __expf(s[nt][0] - mn0);
            float p1 = __expf(s[nt][1] - mn0);
            float p2 = __expf(s[nt][2] - mn1);
            float p3 = __expf(s[nt][3] - mn1);
            sum0 += p0 + p1;
            sum1 += p2 + p3;
            uint2 u01 = make_uint2(f2tf(p0), f2tf(p1));
            uint2 u23 = make_uint2(f2tf(p2), f2tf(p3));
            *(uint2*)&Ps[pr0][nt * 8 + 2 * tig] = u01;
            *(uint2*)&Ps[pr1][nt * 8 + 2 * tig] = u23;
        }
        sum0 += __shfl_xor_sync(0xffffffffu, sum0, 1);
        sum0 += __shfl_xor_sync(0xffffffffu, sum0, 2);
        sum1 += __shfl_xor_sync(0xffffffffu, sum1, 1);
        sum1 += __shfl_xor_sync(0xffffffffu, sum1, 2);
        l0 = l0 * corr0 + sum0;
        l1 = l1 * corr1 + sum1;

#pragma unroll
        for (int nt2 = 0; nt2 < 4; nt2++) {
            oacc[nt2][0] *= corr0; oacc[nt2][1] *= corr0;
            oacc[nt2][2] *= corr1; oacc[nt2][3] *= corr1;
        }
        __syncwarp();   // Ps visible within warp (it is warp-private)

        // --- O += P @ V ---
#pragma unroll
        for (int kc = 0; kc < 8; kc++) {
            unsigned af[4];
            af[0] = Ps[pr0][kc * 8 + tig];
            af[1] = Ps[pr1][kc * 8 + tig];
            af[2] = Ps[pr0][kc * 8 + tig + 4];
            af[3] = Ps[pr1][kc * 8 + tig + 4];
#pragma unroll
            for (int nt2 = 0; nt2 < 4; nt2++) {
                unsigned bf[2];
                bf[0] = Vs[kc * 8 + tig][nt2 * 8 + g];
                bf[1] = Vs[kc * 8 + tig + 4][nt2 * 8 + g];
                mma_tf32(oacc[nt2], af, bf);
            }
        }
    }

    // --- normalize and store ---
    float li0 = 1.f / l0, li1 = 1.f / l1;
#pragma unroll
    for (int nt2 = 0; nt2 < 4; nt2++) {
        int c = h * DK_ + nt2 * 8 + 2 * tig;
        *(float2*)&O[(size_t)(b * M_ + rg) * D_ + c] =
            make_float2(oacc[nt2][0] * li0, oacc[nt2][1] * li0);
        *(float2*)&O[(size_t)(b * M_ + rg + 8) * D_ + c] =
            make_float2(oacc[nt2][2] * li1, oacc[nt2][3] * li1);
    }
}

// ---------------- fused residual + LayerNorm (warp per row) ----------------
__global__ __launch_bounds__(256) void add_ln_kernel(
    const float* __restrict__ xin, const float* __restrict__ res,
    const float* __restrict__ gamma, const float* __restrict__ beta,
    float* __restrict__ xout)
{
    int warp = threadIdx.x >> 5, lane = threadIdx.x & 31;
    int row = blockIdx.x * 8 + warp;

    const float4* px = (const float4*)(xin + (size_t)row * D_) + lane * 2;
    const float4* pr = (const float4*)(res + (size_t)row * D_) + lane * 2;
    float4 x0 = px[0], x1 = px[1], r0 = pr[0], r1 = pr[1];
    float v[8] = { x0.x + r0.x, x0.y + r0.y, x0.z + r0.z, x0.w + r0.w,
                   x1.x + r1.x, x1.y + r1.y, x1.z + r1.z, x1.w + r1.w };

    float s = 0.f, q = 0.f;
#pragma unroll
    for (int c = 0; c < 8; c++) { s += v[c]; q += v[c] * v[c]; }
#pragma unroll
    for (int off = 16; off > 0; off >>= 1) {
        s += __shfl_xor_sync(0xffffffffu, s, off);
        q += __shfl_xor_sync(0xffffffffu, q, off);
    }
    float mu  = s * (1.f / D_);
    float var = q * (1.f / D_) - mu * mu;
    float rs  = rsqrtf(var + LN_EPS);

    const float4* pg = (const float4*)gamma + lane * 2;
    const float4* pb = (const float4*)beta  + lane * 2;
    float4 g0 = pg[0], g1 = pg[1], b0 = pb[0], b1 = pb[1];

    float4 o0, o1;
    o0.x = (v[0] - mu) * rs * g0.x + b0.x;
    o0.y = (v[1] - mu) * rs * g0.y + b0.y;
    o0.z = (v[2] - mu) * rs * g0.z + b0.z;
    o0.w = (v[3] - mu) * rs * g0.w + b0.w;
    o1.x = (v[4] - mu) * rs * g1.x + b1.x;
    o1.y = (v[5] - mu) * rs * g1.y + b1.y;
    o1.z = (v[6] - mu) * rs * g1.z + b1.z;
    o1.w = (v[7] - mu) * rs * g1.w + b1.w;

    float4* po = (float4*)(xout + (size_t)row * D_) + lane * 2;
    po[0] = o0;
    po[1] = o1;
}

// ---------------- host launcher ----------------
extern "C" void kernel_launch(void* const* d_in, const int* in_sizes, int n_in,
                              void* d_out, int out_size)
{
    const float* x      = (const float*)d_in[0];
    const float* coords = (const float*)d_in[1];
    const float* wq     = (const float*)d_in[2];
    const float* bq     = (const float*)d_in[3];
    const float* wk     = (const float*)d_in[4];
    const float* bk     = (const float*)d_in[5];
    const float* wv     = (const float*)d_in[6];
    const float* bv     = (const float*)d_in[7];
    const float* alpha  = (const float*)d_in[8];
    const float* w1     = (const float*)d_in[9];
    const float* b1     = (const float*)d_in[10];
    const float* w2     = (const float*)d_in[11];
    const float* b2     = (const float*)d_in[12];
    const float* ln1g   = (const float*)d_in[13];
    const float* ln1b   = (const float*)d_in[14];
    const float* ln2g   = (const float*)d_in[15];
    const float* ln2b   = (const float*)d_in[16];
    float* out = (float*)d_out;

    float *gx, *gq, *gk, *gv, *gatt, *gff1, *gff2;
    cudaGetSymbolAddress((void**)&gx,   g_x);
    cudaGetSymbolAddress((void**)&gq,   g_q);
    cudaGetSymbolAddress((void**)&gk,   g_k);
    cudaGetSymbolAddress((void**)&gv,   g_v);
    cudaGetSymbolAddress((void**)&gatt, g_att);
    cudaGetSymbolAddress((void**)&gff1, g_ff1);
    cudaGetSymbolAddress((void**)&gff2, g_ff2);

    copy_kernel<<<(R_ * D_ + 255) / 256, 256>>>(x, gx, R_ * D_);

    for (int i = 0; i < L_; i++) {
        dim3 g_qkv(R_ / 128, D_ / 64);
        gemm_tc<<<g_qkv, 256>>>(gx, wq + (size_t)i * D_ * D_, bq + i * D_, gq, D_, D_, 0);
        gemm_tc<<<g_qkv, 256>>>(gx, wk + (size_t)i * D_ * D_, bk + i * D_, gk, D_, D_, 0);
        gemm_tc<<<g_qkv, 256>>>(gx, wv + (size_t)i * D_ * D_, bv + i * D_, gv, D_, D_, 0);

        attn_tc<<<dim3(M_ / 64, B_ * H_), 128>>>(gq, gk, gv, coords, alpha, i, gatt);

        add_ln_kernel<<<R_ / 8, 256>>>(gx, gatt, ln1g + i * D_, ln1b + i * D_, gx);

        gemm_tc<<<dim3(R_ / 128, FF_ / 64), 256>>>(gx, w1 + (size_t)i * D_ * FF_, b1 + i * FF_, gff1, D_, FF_, 1);
        gemm_tc<<<dim3(R_ / 128, D_ / 64), 256>>>(gff1, w2 + (size_t)i * FF_ * D_, b2 + i * D_, gff2, FF_, D_, 0);

        float* xout = (i == L_ - 1) ? out : gx;
        add_ln_kernel<<<R_ / 8, 256>>>(gx, gff2, ln2g + i * D_, ln2b + i * D_, xout);
    }
}

// round 5
// speedup vs baseline: 3.1178x; 1.2116x over previous
#include <cuda_runtime.h>

#define B_ 2
#define M_ 2048
#define D_ 256
#define H_ 8
#define DK_ 32
#define L_ 4
#define FF_ 512
#define R_ (B_*M_)
#define LN_EPS 1e-5f

// attn dynamic smem layout (in unsigned words)
#define KT_WORDS (40*72)
#define VS_WORDS (64*40)
#define PS_WORDS (128*68)
#define ATTN_SMEM_BYTES ((KT_WORDS + VS_WORDS + PS_WORDS) * 4)

// ---------------- scratch (static device globals; no allocation) ----------------
__device__ float g_x  [R_*D_];
__device__ float g_q  [R_*D_];
__device__ float g_k  [R_*D_];
__device__ float g_v  [R_*D_];
__device__ float g_att[R_*D_];
__device__ float g_ff1[R_*FF_];
__device__ float g_ff2[R_*D_];

// ---------------- tf32 helpers ----------------
__device__ __forceinline__ unsigned f2tf(float x) {
    unsigned u;
    asm("cvt.rna.tf32.f32 %0, %1;" : "=r"(u) : "f"(x));
    return u;
}

__device__ __forceinline__ void mma_tf32(float d[4], const unsigned a[4], const unsigned b[2]) {
    asm volatile(
        "mma.sync.aligned.m16n8k8.row.col.f32.tf32.tf32.f32 "
        "{%0,%1,%2,%3}, {%4,%5,%6,%7}, {%8,%9}, {%0,%1,%2,%3};"
        : "+f"(d[0]), "+f"(d[1]), "+f"(d[2]), "+f"(d[3])
        : "r"(a[0]), "r"(a[1]), "r"(a[2]), "r"(a[3]), "r"(b[0]), "r"(b[1]));
}

// ---------------- simple copy ----------------
__global__ void copy_kernel(const float* __restrict__ src, float* __restrict__ dst, int n)
{
    int i = blockIdx.x * blockDim.x + threadIdx.x;
    if (i < n) dst[i] = src[i];
}

// ---------------- TF32 GEMM core: 64x64 tile, BK=32, 128 threads (4 warps 2x2) ----------------
// Register-prefetch pipeline: tile kb+1 loaded to regs during compute of tile kb.
__device__ __forceinline__ void gemm_core(
    const float* __restrict__ A, const float* __restrict__ W,
    const float* __restrict__ bias, float* __restrict__ C,
    int K, int N, int row0, int col0, int relu)
{
    __shared__ unsigned As[64][36];   // stride 36 = 4 mod 32
    __shared__ unsigned Ws[32][72];   // stride 72 = 8 mod 32

    int tid  = threadIdx.x;
    int warp = tid >> 5, lane = tid & 31;
    int g = lane >> 2, tig = lane & 3;
    int wm = warp >> 1, wn = warp & 1;

    int arow = tid >> 1, acol = (tid & 1) * 16;   // A tile: 64x32, 16 floats/thread
    int wrow = tid >> 2, wcol = (tid & 3) * 16;   // W tile: 32x64, 16 floats/thread

    float pa[16], pw[16];
    {
        const float* ap = &A[(size_t)(row0 + arow) * K + acol];
        const float* wp = &W[(size_t)wrow * N + col0 + wcol];
#pragma unroll
        for (int j = 0; j < 16; j += 4) {
            *(float4*)&pa[j] = *(const float4*)(ap + j);
            *(float4*)&pw[j] = *(const float4*)(wp + j);
        }
    }

    float acc[2][4][4] = {};

    for (int kb = 0; kb < K; kb += 32) {
        __syncthreads();   // prior compute done reading smem
#pragma unroll
        for (int j = 0; j < 16; j += 4) {
            uint4 u;
            u.x = f2tf(pa[j]); u.y = f2tf(pa[j+1]); u.z = f2tf(pa[j+2]); u.w = f2tf(pa[j+3]);
            *(uint4*)&As[arow][acol + j] = u;
            uint4 w;
            w.x = f2tf(pw[j]); w.y = f2tf(pw[j+1]); w.z = f2tf(pw[j+2]); w.w = f2tf(pw[j+3]);
            *(uint4*)&Ws[wrow][wcol + j] = w;
        }
        __syncthreads();

        if (kb + 32 < K) {   // prefetch next tile (overlaps MMA below)
            const float* ap = &A[(size_t)(row0 + arow) * K + kb + 32 + acol];
            const float* wp = &W[(size_t)(kb + 32 + wrow) * N + col0 + wcol];
#pragma unroll
            for (int j = 0; j < 16; j += 4) {
                *(float4*)&pa[j] = *(const float4*)(ap + j);
                *(float4*)&pw[j] = *(const float4*)(wp + j);
            }
        }

#pragma unroll
        for (int ks = 0; ks < 4; ks++) {
            unsigned af[2][4];
#pragma unroll
            for (int mt = 0; mt < 2; mt++) {
                int r = wm * 32 + mt * 16;
                af[mt][0] = As[r + g][ks * 8 + tig];
                af[mt][1] = As[r + g + 8][ks * 8 + tig];
                af[mt][2] = As[r + g][ks * 8 + tig + 4];
                af[mt][3] = As[r + g + 8][ks * 8 + tig + 4];
            }
            unsigned bf[4][2];
#pragma unroll
            for (int nt = 0; nt < 4; nt++) {
                int c = wn * 32 + nt * 8;
                bf[nt][0] = Ws[ks * 8 + tig][c + g];
                bf[nt][1] = Ws[ks * 8 + tig + 4][c + g];
            }
#pragma unroll
            for (int mt = 0; mt < 2; mt++)
#pragma unroll
                for (int nt = 0; nt < 4; nt++)
                    mma_tf32(acc[mt][nt], af[mt], bf[nt]);
        }
    }

#pragma unroll
    for (int nt = 0; nt < 4; nt++) {
        int c = col0 + wn * 32 + nt * 8 + 2 * tig;
        float b0 = bias[c], b1 = bias[c + 1];
#pragma unroll
        for (int mt = 0; mt < 2; mt++) {
            int r = row0 + wm * 32 + mt * 16 + g;
            float v0 = acc[mt][nt][0] + b0;
            float v1 = acc[mt][nt][1] + b1;
            float v2 = acc[mt][nt][2] + b0;
            float v3 = acc[mt][nt][3] + b1;
            if (relu) {
                v0 = fmaxf(v0, 0.f); v1 = fmaxf(v1, 0.f);
                v2 = fmaxf(v2, 0.f); v3 = fmaxf(v3, 0.f);
            }
            *(float2*)&C[(size_t)r * N + c]       = make_float2(v0, v1);
            *(float2*)&C[(size_t)(r + 8) * N + c] = make_float2(v2, v3);
        }
    }
}

// generic GEMM wrapper: grid (R/64, N/64)
__global__ __launch_bounds__(128) void gemm64(
    const float* __restrict__ A, const float* __restrict__ W,
    const float* __restrict__ bias, float* __restrict__ C,
    int K, int N, int relu)
{
    gemm_core(A, W, bias, C, K, N, blockIdx.x * 64, blockIdx.y * 64, relu);
}

// fused QKV: grid (R/64, 12); y>>2 selects Q/K/V, y&3 selects column tile
__global__ __launch_bounds__(128) void gemm_qkv(
    const float* __restrict__ A,
    const float* __restrict__ wq, const float* __restrict__ wk, const float* __restrict__ wv,
    const float* __restrict__ bq, const float* __restrict__ bk, const float* __restrict__ bv,
    float* __restrict__ q, float* __restrict__ k, float* __restrict__ v)
{
    int which = blockIdx.y >> 2;
    const float* W    = (which == 0) ? wq : (which == 1) ? wk : wv;
    const float* bias = (which == 0) ? bq : (which == 1) ? bk : bv;
    float* C          = (which == 0) ? q  : (which == 1) ? k  : v;
    gemm_core(A, W, bias, C, D_, D_, blockIdx.x * 64, (blockIdx.y & 3) * 64, 0);
}

// ---------------- TF32 flash attention with fused geometric bias ----------------
// scores = (q.k)/sqrt(dk) + alpha*(cq.ck). Q pre-scaled; k-dims 32..34 carry
// alpha*coords (Q side) / coords (K side); dims 35..39 zero pad (K=40).
// grid: (M/128, B*H), 256 threads (8 warps x 16 query rows). Next K/V tile
// register-prefetched during current tile's MMAs. Dynamic smem (56.5KB).
__global__ __launch_bounds__(256) void attn_tc(
    const float* __restrict__ Q, const float* __restrict__ Kg,
    const float* __restrict__ V, const float* __restrict__ coords,
    const float* __restrict__ alpha_arr, int layer, float* __restrict__ O)
{
    extern __shared__ unsigned sm_[];
    unsigned (*Kt)[72] = (unsigned(*)[72])sm_;                          // [40][72]
    unsigned (*Vs)[40] = (unsigned(*)[40])(sm_ + KT_WORDS);             // [64][40]
    unsigned (*Ps)[68] = (unsigned(*)[68])(sm_ + KT_WORDS + VS_WORDS);  // [128][68]

    int tid  = threadIdx.x;
    int warp = tid >> 5, lane = tid & 31;
    int g = lane >> 2, tig = lane & 3;
    int bh = blockIdx.y, b = bh >> 3, h = bh & 7;
    int q0 = blockIdx.x * 128;
    const float scale = 0.17677669529663687f;  // 1/sqrt(32)
    float alpha = __ldg(alpha_arr + layer);

    int rg  = q0 + warp * 16 + g;       // this thread's two query rows: rg, rg+8
    size_t qbase = (size_t)(b * M_ + rg) * D_ + h * DK_;

    // --- Q fragments in registers (constant across K loop) ---
    unsigned qa[5][4];
#pragma unroll
    for (int ks = 0; ks < 4; ks++) {
        int c0 = ks * 8 + tig;
        qa[ks][0] = f2tf(Q[qbase + c0] * scale);
        qa[ks][1] = f2tf(Q[qbase + 8 * (size_t)D_ + c0] * scale);
        qa[ks][2] = f2tf(Q[qbase + c0 + 4] * scale);
        qa[ks][3] = f2tf(Q[qbase + 8 * (size_t)D_ + c0 + 4] * scale);
    }
    {
        float v0 = (tig < 3) ? alpha * coords[(size_t)(b * M_ + rg) * 3 + tig] : 0.f;
        float v1 = (tig < 3) ? alpha * coords[(size_t)(b * M_ + rg + 8) * 3 + tig] : 0.f;
        qa[4][0] = f2tf(v0);
        qa[4][1] = f2tf(v1);
        qa[4][2] = 0u;
        qa[4][3] = 0u;
    }

    // zero pad rows of Kt (written once; never overwritten)
    if (tid < 64) {
        Kt[35][tid] = 0u; Kt[36][tid] = 0u; Kt[37][tid] = 0u;
        Kt[38][tid] = 0u; Kt[39][tid] = 0u;
    }

    float m0 = -1e30f, m1 = -1e30f, l0 = 0.f, l1 = 0.f;
    float oacc[4][4] = {};

    // K/V tile loader: thread handles row (tid&63), 8 cols from (tid>>6)*8
    int ldr = tid & 63;
    int ldc = (tid >> 6) * 8;
    size_t kvbase = (size_t)(b * M_) * D_ + h * DK_;

    float kf[8], vf[8], cf0 = 0.f, cf1 = 0.f, cf2 = 0.f;
    {
        const float* kp = &Kg[kvbase + (size_t)ldr * D_ + ldc];
        *(float4*)&kf[0] = *(const float4*)kp;
        *(float4*)&kf[4] = *(const float4*)(kp + 4);
        const float* vp = &V[kvbase + (size_t)ldr * D_ + ldc];
        *(float4*)&vf[0] = *(const float4*)vp;
        *(float4*)&vf[4] = *(const float4*)(vp + 4);
        if (tid < 64) {
            const float* cp = &coords[(size_t)(b * M_ + tid) * 3];
            cf0 = cp[0]; cf1 = cp[1]; cf2 = cp[2];
        }
    }

    int pr0 = warp * 16 + g, pr1 = pr0 + 8;

    for (int kt = 0; kt < M_ / 64; kt++) {
        __syncthreads();   // prev iter's MMA reads of Kt/Vs done

        // --- store prefetched K (transposed) and V into smem ---
#pragma unroll
        for (int j = 0; j < 8; j++) Kt[ldc + j][ldr] = f2tf(kf[j]);
        {
            uint4 u;
            u.x = f2tf(vf[0]); u.y = f2tf(vf[1]); u.z = f2tf(vf[2]); u.w = f2tf(vf[3]);
            *(uint4*)&Vs[ldr][ldc] = u;
            u.x = f2tf(vf[4]); u.y = f2tf(vf[5]); u.z = f2tf(vf[6]); u.w = f2tf(vf[7]);
            *(uint4*)&Vs[ldr][ldc + 4] = u;
        }
        if (tid < 64) {
            Kt[32][tid] = f2tf(cf0);
            Kt[33][tid] = f2tf(cf1);
            Kt[34][tid] = f2tf(cf2);
        }
        __syncthreads();

        // --- prefetch next tile (overlaps all MMA/softmax below) ---
        if (kt + 1 < M_ / 64) {
            int k0n = (kt + 1) * 64;
            const float* kp = &Kg[kvbase + (size_t)(k0n + ldr) * D_ + ldc];
            *(float4*)&kf[0] = *(const float4*)kp;
            *(float4*)&kf[4] = *(const float4*)(kp + 4);
            const float* vp = &V[kvbase + (size_t)(k0n + ldr) * D_ + ldc];
            *(float4*)&vf[0] = *(const float4*)vp;
            *(float4*)&vf[4] = *(const float4*)(vp + 4);
            if (tid < 64) {
                const float* cp = &coords[(size_t)(b * M_ + k0n + tid) * 3];
                cf0 = cp[0]; cf1 = cp[1]; cf2 = cp[2];
            }
        }

        // --- S = Q K^T + bias ---
        float s[8][4] = {};
#pragma unroll
        for (int nt = 0; nt < 8; nt++) {
#pragma unroll
            for (int ks = 0; ks < 5; ks++) {
                unsigned bf[2];
                bf[0] = Kt[ks * 8 + tig][nt * 8 + g];
                bf[1] = Kt[ks * 8 + tig + 4][nt * 8 + g];
                mma_tf32(s[nt], qa[ks], bf);
            }
        }

        // --- online softmax (rows rg, rg+8; 4 tig lanes share each row) ---
        float mx0 = -1e30f, mx1 = -1e30f;
#pragma unroll
        for (int nt = 0; nt < 8; nt++) {
            mx0 = fmaxf(mx0, fmaxf(s[nt][0], s[nt][1]));
            mx1 = fmaxf(mx1, fmaxf(s[nt][2], s[nt][3]));
        }
        mx0 = fmaxf(mx0, __shfl_xor_sync(0xffffffffu, mx0, 1));
        mx0 = fmaxf(mx0, __shfl_xor_sync(0xffffffffu, mx0, 2));
        mx1 = fmaxf(mx1, __shfl_xor_sync(0xffffffffu, mx1, 1));
        mx1 = fmaxf(mx1, __shfl_xor_sync(0xffffffffu, mx1, 2));

        float mn0 = fmaxf(m0, mx0), mn1 = fmaxf(m1, mx1);
        float corr0 = __expf(m0 - mn0), corr1 = __expf(m1 - mn1);
        m0 = mn0; m1 = mn1;

        float sum0 = 0.f, sum1 = 0.f;
#pragma unroll
        for (int nt = 0; nt < 8; nt++) {
            float p0 = __expf(s[nt][0] - mn0);
            float p1 = __expf(s[nt][1] - mn0);
            float p2 = __expf(s[nt][2] - mn1);
            float p3 = __expf(s[nt][3] - mn1);
            sum0 += p0 + p1;
            sum1 += p2 + p3;
            *(uint2*)&Ps[pr0][nt * 8 + 2 * tig] = make_uint2(f2tf(p0), f2tf(p1));
            *(uint2*)&Ps[pr1][nt * 8 + 2 * tig] = make_uint2(f2tf(p2), f2tf(p3));
        }
        sum0 += __shfl_xor_sync(0xffffffffu, sum0, 1);
        sum0 += __shfl_xor_sync(0xffffffffu, sum0, 2);
        sum1 += __shfl_xor_sync(0xffffffffu, sum1, 1);
        sum1 += __shfl_xor_sync(0xffffffffu, sum1, 2);
        l0 = l0 * corr0 + sum0;
        l1 = l1 * corr1 + sum1;

#pragma unroll
        for (int nt2 = 0; nt2 < 4; nt2++) {
            oacc[nt2][0] *= corr0; oacc[nt2][1] *= corr0;
            oacc[nt2][2] *= corr1; oacc[nt2][3] *= corr1;
        }
        __syncwarp();   // Ps band is warp-private

        // --- O += P @ V ---
#pragma unroll
        for (int kc = 0; kc < 8; kc++) {
            unsigned af[4];
            af[0] = Ps[pr0][kc * 8 + tig];
            af[1] = Ps[pr1][kc * 8 + tig];
            af[2] = Ps[pr0][kc * 8 + tig + 4];
            af[3] = Ps[pr1][kc * 8 + tig + 4];
#pragma unroll
            for (int nt2 = 0; nt2 < 4; nt2++) {
                unsigned bf[2];
                bf[0] = Vs[kc * 8 + tig][nt2 * 8 + g];
                bf[1] = Vs[kc * 8 + tig + 4][nt2 * 8 + g];
                mma_tf32(oacc[nt2], af, bf);
            }
        }
    }

    // --- normalize and store ---
    float li0 = 1.f / l0, li1 = 1.f / l1;
#pragma unroll
    for (int nt2 = 0; nt2 < 4; nt2++) {
        int c = h * DK_ + nt2 * 8 + 2 * tig;
        *(float2*)&O[(size_t)(b * M_ + rg) * D_ + c] =
            make_float2(oacc[nt2][0] * li0, oacc[nt2][1] * li0);
        *(float2*)&O[(size_t)(b * M_ + rg + 8) * D_ + c] =
            make_float2(oacc[nt2][2] * li1, oacc[nt2][3] * li1);
    }
}

// ---------------- fused residual + LayerNorm (warp per row) ----------------
__global__ __launch_bounds__(256) void add_ln_kernel(
    const float* __restrict__ xin, const float* __restrict__ res,
    const float* __restrict__ gamma, const float* __restrict__ beta,
    float* __restrict__ xout)
{
    int warp = threadIdx.x >> 5, lane = threadIdx.x & 31;
    int row = blockIdx.x * 8 + warp;

    const float4* px = (const float4*)(xin + (size_t)row * D_) + lane * 2;
    const float4* pr = (const float4*)(res + (size_t)row * D_) + lane * 2;
    float4 x0 = px[0], x1 = px[1], r0 = pr[0], r1 = pr[1];
    float v[8] = { x0.x + r0.x, x0.y + r0.y, x0.z + r0.z, x0.w + r0.w,
                   x1.x + r1.x, x1.y + r1.y, x1.z + r1.z, x1.w + r1.w };

    float s = 0.f, q = 0.f;
#pragma unroll
    for (int c = 0; c < 8; c++) { s += v[c]; q += v[c] * v[c]; }
#pragma unroll
    for (int off = 16; off > 0; off >>= 1) {
        s += __shfl_xor_sync(0xffffffffu, s, off);
        q += __shfl_xor_sync(0xffffffffu, q, off);
    }
    float mu  = s * (1.f / D_);
    float var = q * (1.f / D_) - mu * mu;
    float rs  = rsqrtf(var + LN_EPS);

    const float4* pg = (const float4*)gamma + lane * 2;
    const float4* pb = (const float4*)beta  + lane * 2;
    float4 g0 = pg[0], g1 = pg[1], b0 = pb[0], b1 = pb[1];

    float4 o0, o1;
    o0.x = (v[0] - mu) * rs * g0.x + b0.x;
    o0.y = (v[1] - mu) * rs * g0.y + b0.y;
    o0.z = (v[2] - mu) * rs * g0.z + b0.z;
    o0.w = (v[3] - mu) * rs * g0.w + b0.w;
    o1.x = (v[4] - mu) * rs * g1.x + b1.x;
    o1.y = (v[5] - mu) * rs * g1.y + b1.y;
    o1.z = (v[6] - mu) * rs * g1.z + b1.z;
    o1.w = (v[7] - mu) * rs * g1.w + b1.w;

    float4* po = (float4*)(xout + (size_t)row * D_) + lane * 2;
    po[0] = o0;
    po[1] = o1;
}

// ---------------- host launcher ----------------
extern "C" void kernel_launch(void* const* d_in, const int* in_sizes, int n_in,
                              void* d_out, int out_size)
{
    const float* x      = (const float*)d_in[0];
    const float* coords = (const float*)d_in[1];
    const float* wq     = (const float*)d_in[2];
    const float* bq     = (const float*)d_in[3];
    const float* wk     = (const float*)d_in[4];
    const float* bk     = (const float*)d_in[5];
    const float* wv     = (const float*)d_in[6];
    const float* bv     = (const float*)d_in[7];
    const float* alpha  = (const float*)d_in[8];
    const float* w1     = (const float*)d_in[9];
    const float* b1     = (const float*)d_in[10];
    const float* w2     = (const float*)d_in[11];
    const float* b2     = (const float*)d_in[12];
    const float* ln1g   = (const float*)d_in[13];
    const float* ln1b   = (const float*)d_in[14];
    const float* ln2g   = (const float*)d_in[15];
    const float* ln2b   = (const float*)d_in[16];
    float* out = (float*)d_out;

    float *gx, *gq, *gk, *gv, *gatt, *gff1, *gff2;
    cudaGetSymbolAddress((void**)&gx,   g_x);
    cudaGetSymbolAddress((void**)&gq,   g_q);
    cudaGetSymbolAddress((void**)&gk,   g_k);
    cudaGetSymbolAddress((void**)&gv,   g_v);
    cudaGetSymbolAddress((void**)&gatt, g_att);
    cudaGetSymbolAddress((void**)&gff1, g_ff1);
    cudaGetSymbolAddress((void**)&gff2, g_ff2);

    // allow >48KB dynamic smem for attn (idempotent; legal under graph capture)
    cudaFuncSetAttribute(attn_tc, cudaFuncAttributeMaxDynamicSharedMemorySize,
                         ATTN_SMEM_BYTES);

    copy_kernel<<<(R_ * D_ + 255) / 256, 256>>>(x, gx, R_ * D_);

    for (int i = 0; i < L_; i++) {
        gemm_qkv<<<dim3(R_ / 64, 12), 128>>>(
            gx,
            wq + (size_t)i * D_ * D_, wk + (size_t)i * D_ * D_, wv + (size_t)i * D_ * D_,
            bq + i * D_, bk + i * D_, bv + i * D_,
            gq, gk, gv);

        attn_tc<<<dim3(M_ / 128, B_ * H_), 256, ATTN_SMEM_BYTES>>>(
            gq, gk, gv, coords, alpha, i, gatt);

        add_ln_kernel<<<R_ / 8, 256>>>(gx, gatt, ln1g + i * D_, ln1b + i * D_, gx);

        gemm64<<<dim3(R_ / 64, FF_ / 64), 128>>>(gx, w1 + (size_t)i * D_ * FF_, b1 + i * FF_, gff1, D_, FF_, 1);
        gemm64<<<dim3(R_ / 64, D_ / 64), 128>>>(gff1, w2 + (size_t)i * FF_ * D_, b2 + i * D_, gff2, FF_, D_, 0);

        float* xout = (i == L_ - 1) ? out : gx;
        add_ln_kernel<<<R_ / 8, 256>>>(gx, gff2, ln2g + i * D_, ln2b + i * D_, xout);
    }
}